// round 10
// baseline (speedup 1.0000x reference)
#include <cuda_runtime.h>
#include <cuda_fp16.h>
#include <cuda_bf16.h>
#include <cstdint>

// Problem constants (fixed instance)
#define DM   128      // model dim
#define HH   8        // heads
#define MV   3        // views
#define MAXN 100000
#define MAXE 1600000

typedef unsigned long long ull;

// ---------------- scratch (static __device__ — no allocations) ----------------
__device__ float  g_q[(size_t)MAXN * DM];
// interleaved K/V in fp16: per node, 32 slots of 16B: {k01,k23,v01,v23}
__device__ uint4  g_kv[(size_t)MAXN * 32];
__device__ float  g_inv[(size_t)MAXN * HH];  // per (node, head) 1/sum
__device__ int    g_count[MAXN];
__device__ int    g_rowptr[MAXN + 1];
__device__ int    g_rowfill[MAXN];
__device__ int    g_bsum[128];
__device__ int    g_boff[128];
__device__ int2   g_elist[MAXE];             // (edge_id, src)
// W^T tiles, bf16: [mat(3)][split(2)][n(128)][k(128)]
__device__ __nv_bfloat16 g_wt[6 * 16384];

__device__ __forceinline__ uint32_t packbf2(float a, float b) {
    __nv_bfloat162 t = __floats2bfloat162_rn(a, b);
    return *(uint32_t*)&t;
}

// ---------------- W prep: transpose + bf16 hi/lo split ----------------
__global__ void prep_w_kernel(const float* __restrict__ Wq, const float* __restrict__ Wk,
                              const float* __restrict__ Wv) {
    const int idx = blockIdx.x * blockDim.x + threadIdx.x;
    if (idx >= 6 * 16384) return;
    const int ms  = idx >> 14;         // mat*2 + split
    const int rem = idx & 16383;
    const int nrow = rem >> 7;         // output column (B row) 0..127
    const int kcol = rem & 127;        // K 0..127
    const int m = ms >> 1, s = ms & 1;
    const float* W = (m == 0) ? Wq : ((m == 1) ? Wk : Wv);
    const float val = W[kcol * DM + nrow];   // stored as WT[n][k]
    __nv_bfloat16 h = __float2bfloat16(val);
    if (s == 1) h = __float2bfloat16(val - __bfloat162float(h));
    g_wt[(size_t)ms * 16384 + nrow * 128 + kcol] = h;
}

// ---------------- tensor-core QKV via baseline mma.sync (bf16 split, f32 accum) ----------------
#define XPAD 136
#define QKV_SMEM_ELEMS (4 * 128 * XPAD)
#define QKV_SMEM_BYTES (QKV_SMEM_ELEMS * 2)

__device__ __forceinline__ void mma16816(float* c, const uint32_t* a, const uint32_t* b) {
    asm volatile(
        "mma.sync.aligned.m16n8k16.row.col.f32.bf16.bf16.f32 "
        "{%0,%1,%2,%3}, {%4,%5,%6,%7}, {%8,%9}, {%0,%1,%2,%3};"
        : "+f"(c[0]), "+f"(c[1]), "+f"(c[2]), "+f"(c[3])
        : "r"(a[0]), "r"(a[1]), "r"(a[2]), "r"(a[3]), "r"(b[0]), "r"(b[1]));
}

__global__ __launch_bounds__(256, 1) void qkv_mma_kernel(
    const float* __restrict__ x,
    const float* __restrict__ bq, const float* __restrict__ bk, const float* __restrict__ bv,
    int n)
{
    extern __shared__ __nv_bfloat16 sm[];
    __nv_bfloat16* sxh = sm;
    __nv_bfloat16* sxl = sm + 128 * XPAD;
    __nv_bfloat16* swh = sm + 2 * 128 * XPAD;
    __nv_bfloat16* swl = sm + 3 * 128 * XPAD;

    const int tid = threadIdx.x;
    const int wid = tid >> 5;
    const int lane = tid & 31;
    const int wm = wid & 1;
    const int wn = wid >> 1;
    const int g = lane >> 2;
    const int tig = lane & 3;
    const int row0 = blockIdx.x * 128;

    // phase 1: load X tile, bf16 hi/lo split into SMEM
    for (int t = tid; t < 128 * 32; t += 256) {
        const int r = t >> 5, c4 = (t & 31) * 4;
        const int row = row0 + r;
        float4 f = make_float4(0.f, 0.f, 0.f, 0.f);
        if (row < n) f = *(const float4*)(x + (size_t)row * DM + c4);
        const __nv_bfloat16 h0 = __float2bfloat16(f.x), h1 = __float2bfloat16(f.y);
        const __nv_bfloat16 h2 = __float2bfloat16(f.z), h3 = __float2bfloat16(f.w);
        const int base = r * XPAD + c4;
        *(uint32_t*)(sxh + base)     = packbf2(__bfloat162float(h0), __bfloat162float(h1));
        *(uint32_t*)(sxh + base + 2) = packbf2(__bfloat162float(h2), __bfloat162float(h3));
        *(uint32_t*)(sxl + base)     = packbf2(f.x - __bfloat162float(h0), f.y - __bfloat162float(h1));
        *(uint32_t*)(sxl + base + 2) = packbf2(f.z - __bfloat162float(h2), f.w - __bfloat162float(h3));
    }

    for (int m = 0; m < 3; m++) {
        __syncthreads();
        {
            const uint4* wh = (const uint4*)(g_wt + (size_t)(m * 2) * 16384);
            const uint4* wl = (const uint4*)(g_wt + (size_t)(m * 2 + 1) * 16384);
            for (int t = tid; t < 2048; t += 256) {
                const int r = t >> 4, seg = (t & 15) * 8;
                *(uint4*)(swh + r * XPAD + seg) = wh[t];
                *(uint4*)(swl + r * XPAD + seg) = wl[t];
            }
        }
        __syncthreads();

        float acc[4][4][4];
#pragma unroll
        for (int mf = 0; mf < 4; mf++)
#pragma unroll
            for (int nf = 0; nf < 4; nf++)
#pragma unroll
                for (int r = 0; r < 4; r++) acc[mf][nf][r] = 0.f;

#pragma unroll
        for (int s = 0; s < 3; s++) {  // (hi,hi), (hi,lo), (lo,hi)
            const __nv_bfloat16* A = (s == 2) ? sxl : sxh;
            const __nv_bfloat16* B = (s == 1) ? swl : swh;
#pragma unroll
            for (int ks = 0; ks < 8; ks++) {
                const int kb = ks * 16 + 2 * tig;
                uint32_t a[4][4], b[4][2];
#pragma unroll
                for (int mf = 0; mf < 4; mf++) {
                    const int ar = wm * 64 + mf * 16 + g;
                    a[mf][0] = *(const uint32_t*)(A + ar * XPAD + kb);
                    a[mf][1] = *(const uint32_t*)(A + (ar + 8) * XPAD + kb);
                    a[mf][2] = *(const uint32_t*)(A + ar * XPAD + kb + 8);
                    a[mf][3] = *(const uint32_t*)(A + (ar + 8) * XPAD + kb + 8);
                }
#pragma unroll
                for (int nf = 0; nf < 4; nf++) {
                    const int br = wn * 32 + nf * 8 + g;
                    b[nf][0] = *(const uint32_t*)(B + br * XPAD + kb);
                    b[nf][1] = *(const uint32_t*)(B + br * XPAD + kb + 8);
                }
#pragma unroll
                for (int mf = 0; mf < 4; mf++)
#pragma unroll
                    for (int nf = 0; nf < 4; nf++)
                        mma16816(acc[mf][nf], a[mf], b[nf]);
            }
        }

        const float* bias = (m == 0) ? bq : ((m == 1) ? bk : bv);
        const int hoff = (m == 1) ? 0 : 2;
#pragma unroll
        for (int mf = 0; mf < 4; mf++) {
            const int row = row0 + wm * 64 + mf * 16 + g;
#pragma unroll
            for (int nf = 0; nf < 4; nf++) {
                const int col = wn * 32 + nf * 8 + 2 * tig;
                const float bz0 = bias[col], bz1 = bias[col + 1];
                const float f0 = acc[mf][nf][0] + bz0, f1 = acc[mf][nf][1] + bz1;
                const float f2 = acc[mf][nf][2] + bz0, f3 = acc[mf][nf][3] + bz1;
                if (m == 0) {
                    if (row < n)     *(float2*)(g_q + (size_t)row * DM + col)       = make_float2(f0, f1);
                    if (row + 8 < n) *(float2*)(g_q + (size_t)(row + 8) * DM + col) = make_float2(f2, f3);
                } else {
                    const int word = hoff + ((col >> 1) & 1);
                    if (row < n)
                        ((__half2*)&g_kv[(size_t)row * 32 + (col >> 2)])[word] = __floats2half2_rn(f0, f1);
                    if (row + 8 < n)
                        ((__half2*)&g_kv[(size_t)(row + 8) * 32 + (col >> 2)])[word] = __floats2half2_rn(f2, f3);
                }
            }
        }
    }
}

// ---------------- CSR build ----------------
__global__ void zero_count_kernel(int n) {
    int i = blockIdx.x * blockDim.x + threadIdx.x;
    if (i < n) g_count[i] = 0;
}

// int4 loads: 4 destinations per thread
__global__ void hist_kernel(const int* __restrict__ dst, int e) {
    const int e4 = e >> 2;
    for (int i = blockIdx.x * blockDim.x + threadIdx.x; i < e4; i += gridDim.x * blockDim.x) {
        const int4 d = ((const int4*)dst)[i];
        atomicAdd(&g_count[d.x], 1);
        atomicAdd(&g_count[d.y], 1);
        atomicAdd(&g_count[d.z], 1);
        atomicAdd(&g_count[d.w], 1);
    }
    // tail
    const int base = e4 << 2;
    const int t = blockIdx.x * blockDim.x + threadIdx.x;
    if (t < e - base) atomicAdd(&g_count[dst[base + t]], 1);
}

__global__ __launch_bounds__(1024) void blockscan_kernel(int n) {
    __shared__ int s_wsum[32];
    const int tid = threadIdx.x;
    const int lane = tid & 31, wid = tid >> 5;
    const int i = blockIdx.x * 1024 + tid;
    int v = (i < n) ? g_count[i] : 0;
    int x = v;
#pragma unroll
    for (int o = 1; o < 32; o <<= 1) {
        int t = __shfl_up_sync(0xffffffffu, x, o);
        if (lane >= o) x += t;
    }
    if (lane == 31) s_wsum[wid] = x;
    __syncthreads();
    if (wid == 0) {
        int ws = s_wsum[lane];
#pragma unroll
        for (int o = 1; o < 32; o <<= 1) {
            int t = __shfl_up_sync(0xffffffffu, ws, o);
            if (lane >= o) ws += t;
        }
        s_wsum[lane] = ws;
    }
    __syncthreads();
    int excl = (wid ? s_wsum[wid - 1] : 0) + (x - v);
    if (i < n) g_rowptr[i] = excl;
    if (tid == 0) g_bsum[blockIdx.x] = s_wsum[31];
}

__global__ void bsumscan_kernel(int nb, int n) {
    const int lane = threadIdx.x;
    int carry = 0;
    for (int base = 0; base < nb; base += 32) {
        int idx = base + lane;
        int v = (idx < nb) ? g_bsum[idx] : 0;
        int x = v;
#pragma unroll
        for (int o = 1; o < 32; o <<= 1) {
            int t = __shfl_up_sync(0xffffffffu, x, o);
            if (lane >= o) x += t;
        }
        if (idx < nb) g_boff[idx] = carry + (x - v);
        carry += __shfl_sync(0xffffffffu, x, 31);
    }
    if (lane == 0) g_rowptr[n] = carry;
}

__global__ void addoff_kernel(int n) {
    int i = blockIdx.x * blockDim.x + threadIdx.x;
    if (i < n) {
        int r = g_rowptr[i] + g_boff[i >> 10];
        g_rowptr[i] = r;
        g_rowfill[i] = r;
    }
}

// int4 loads: 4 edges per thread
__global__ void scatter_kernel(const int* __restrict__ src, const int* __restrict__ dst, int e) {
    const int e4 = e >> 2;
    for (int i = blockIdx.x * blockDim.x + threadIdx.x; i < e4; i += gridDim.x * blockDim.x) {
        const int4 d = ((const int4*)dst)[i];
        const int4 s = ((const int4*)src)[i];
        const int eb = i << 2;
        g_elist[atomicAdd(&g_rowfill[d.x], 1)] = make_int2(eb,     s.x);
        g_elist[atomicAdd(&g_rowfill[d.y], 1)] = make_int2(eb + 1, s.y);
        g_elist[atomicAdd(&g_rowfill[d.z], 1)] = make_int2(eb + 2, s.z);
        g_elist[atomicAdd(&g_rowfill[d.w], 1)] = make_int2(eb + 3, s.w);
    }
    const int base = e4 << 2;
    const int t = blockIdx.x * blockDim.x + threadIdx.x;
    if (t < e - base) {
        const int i = base + t;
        g_elist[atomicAdd(&g_rowfill[dst[i]], 1)] = make_int2(i, src[i]);
    }
}

// ---------------- single-pass node kernel: 4-edge unroll, streaming hints ----------------
// One warp per node. Lane l owns features [4l,4l+4), head h = l>>2.
__global__ __launch_bounds__(256) void node_kernel(
    const float* __restrict__ pi,
    const float* __restrict__ view_w,
    float* __restrict__ out_states,   // [N, 128]
    float* __restrict__ out_attn,     // [E, 8] (unnormalized here)
    int n)
{
    const int nd = blockIdx.x * (blockDim.x >> 5) + (threadIdx.x >> 5);
    if (nd >= n) return;
    const int lane = threadIdx.x & 31;
    const unsigned FULL = 0xffffffffu;

    const int beg = g_rowptr[nd];
    const int end = g_rowptr[nd + 1];

    const float4 qv = __ldcs((const float4*)(g_q + (size_t)nd * DM + lane * 4));
    const int h = lane >> 2;
    const float* pip = pi + (size_t)nd * (HH * MV) + h * MV;
    const float pi0 = pip[0], pi1 = pip[1], pi2 = pip[2];

    float ssum = 0.f;
    float4 acc = make_float4(0.f, 0.f, 0.f, 0.f);
    const int wsrc = (lane & 7) * 4;   // shuffle source for per-head w

    int i = beg;
    const int end4 = beg + ((end - beg) & ~3);
    for (; i < end4; i += 4) {
        // front-batched loads: 4 elist + 4 kv gathers in flight
        const int2 e0 = __ldcs(&g_elist[i]);
        const int2 e1 = __ldcs(&g_elist[i + 1]);
        const int2 e2 = __ldcs(&g_elist[i + 2]);
        const int2 e3 = __ldcs(&g_elist[i + 3]);
        const uint4 kv0 = g_kv[(size_t)e0.y * 32 + lane];
        const uint4 kv1 = g_kv[(size_t)e1.y * 32 + lane];
        const uint4 kv2 = g_kv[(size_t)e2.y * 32 + lane];
        const uint4 kv3 = g_kv[(size_t)e3.y * 32 + lane];
        const float* vw0 = view_w + (size_t)e0.x * MV;
        const float* vw1 = view_w + (size_t)e1.x * MV;
        const float* vw2 = view_w + (size_t)e2.x * MV;
        const float* vw3 = view_w + (size_t)e3.x * MV;
        const float mix0 = pi0 * vw0[0] + pi1 * vw0[1] + pi2 * vw0[2];
        const float mix1 = pi0 * vw1[0] + pi1 * vw1[1] + pi2 * vw1[2];
        const float mix2 = pi0 * vw2[0] + pi1 * vw2[1] + pi2 * vw2[2];
        const float mix3 = pi0 * vw3[0] + pi1 * vw3[1] + pi2 * vw3[2];

        float2 ka, kb;
        ka = __half22float2(*(const __half2*)&kv0.x); kb = __half22float2(*(const __half2*)&kv0.y);
        float p0 = qv.x * ka.x + qv.y * ka.y + qv.z * kb.x + qv.w * kb.y;
        ka = __half22float2(*(const __half2*)&kv1.x); kb = __half22float2(*(const __half2*)&kv1.y);
        float p1 = qv.x * ka.x + qv.y * ka.y + qv.z * kb.x + qv.w * kb.y;
        ka = __half22float2(*(const __half2*)&kv2.x); kb = __half22float2(*(const __half2*)&kv2.y);
        float p2 = qv.x * ka.x + qv.y * ka.y + qv.z * kb.x + qv.w * kb.y;
        ka = __half22float2(*(const __half2*)&kv3.x); kb = __half22float2(*(const __half2*)&kv3.y);
        float p3 = qv.x * ka.x + qv.y * ka.y + qv.z * kb.x + qv.w * kb.y;

        p0 += __shfl_xor_sync(FULL, p0, 1);
        p1 += __shfl_xor_sync(FULL, p1, 1);
        p2 += __shfl_xor_sync(FULL, p2, 1);
        p3 += __shfl_xor_sync(FULL, p3, 1);
        p0 += __shfl_xor_sync(FULL, p0, 2);
        p1 += __shfl_xor_sync(FULL, p1, 2);
        p2 += __shfl_xor_sync(FULL, p2, 2);
        p3 += __shfl_xor_sync(FULL, p3, 2);

        const float w0 = (mix0 > 0.f) ? __expf(p0 * 0.25f) * fmaxf(mix0, 1e-8f) : 0.f;
        const float w1 = (mix1 > 0.f) ? __expf(p1 * 0.25f) * fmaxf(mix1, 1e-8f) : 0.f;
        const float w2 = (mix2 > 0.f) ? __expf(p2 * 0.25f) * fmaxf(mix2, 1e-8f) : 0.f;
        const float w3 = (mix3 > 0.f) ? __expf(p3 * 0.25f) * fmaxf(mix3, 1e-8f) : 0.f;
        ssum += (w0 + w1) + (w2 + w3);

        const float wl0 = __shfl_sync(FULL, w0, wsrc);
        const float wl1 = __shfl_sync(FULL, w1, wsrc);
        const float wl2 = __shfl_sync(FULL, w2, wsrc);
        const float wl3 = __shfl_sync(FULL, w3, wsrc);
        if (lane < 8) {
            __stcs(&out_attn[(size_t)e0.x * HH + lane], wl0);
            __stcs(&out_attn[(size_t)e1.x * HH + lane], wl1);
            __stcs(&out_attn[(size_t)e2.x * HH + lane], wl2);
            __stcs(&out_attn[(size_t)e3.x * HH + lane], wl3);
        }

        float2 va, vb;
        va = __half22float2(*(const __half2*)&kv0.z); vb = __half22float2(*(const __half2*)&kv0.w);
        acc.x += va.x * w0; acc.y += va.y * w0; acc.z += vb.x * w0; acc.w += vb.y * w0;
        va = __half22float2(*(const __half2*)&kv1.z); vb = __half22float2(*(const __half2*)&kv1.w);
        acc.x += va.x * w1; acc.y += va.y * w1; acc.z += vb.x * w1; acc.w += vb.y * w1;
        va = __half22float2(*(const __half2*)&kv2.z); vb = __half22float2(*(const __half2*)&kv2.w);
        acc.x += va.x * w2; acc.y += va.y * w2; acc.z += vb.x * w2; acc.w += vb.y * w2;
        va = __half22float2(*(const __half2*)&kv3.z); vb = __half22float2(*(const __half2*)&kv3.w);
        acc.x += va.x * w3; acc.y += va.y * w3; acc.z += vb.x * w3; acc.w += vb.y * w3;
    }
    for (; i < end; i++) {
        const int2 e0 = __ldcs(&g_elist[i]);
        const uint4 kv0 = g_kv[(size_t)e0.y * 32 + lane];
        const float* vw0 = view_w + (size_t)e0.x * MV;
        const float mix0 = pi0 * vw0[0] + pi1 * vw0[1] + pi2 * vw0[2];
        const float2 ka = __half22float2(*(const __half2*)&kv0.x);
        const float2 kb = __half22float2(*(const __half2*)&kv0.y);
        float p0 = qv.x * ka.x + qv.y * ka.y + qv.z * kb.x + qv.w * kb.y;
        p0 += __shfl_xor_sync(FULL, p0, 1);
        p0 += __shfl_xor_sync(FULL, p0, 2);
        const float w0 = (mix0 > 0.f) ? __expf(p0 * 0.25f) * fmaxf(mix0, 1e-8f) : 0.f;
        ssum += w0;
        const float wl0 = __shfl_sync(FULL, w0, wsrc);
        if (lane < 8) __stcs(&out_attn[(size_t)e0.x * HH + lane], wl0);
        const float2 va = __half22float2(*(const __half2*)&kv0.z);
        const float2 vb = __half22float2(*(const __half2*)&kv0.w);
        acc.x += va.x * w0; acc.y += va.y * w0; acc.z += vb.x * w0; acc.w += vb.y * w0;
    }

    const float inv = 1.f / fmaxf(ssum, 1e-8f);
    acc.x *= inv; acc.y *= inv; acc.z *= inv; acc.w *= inv;
    __stcs((float4*)(out_states + (size_t)nd * DM + lane * 4), acc);

    const float inv_h = __shfl_sync(FULL, inv, lane * 4);  // valid for lane<8
    if (lane < 8) g_inv[(size_t)nd * HH + lane] = inv_h;
}

// ---------------- edge-parallel attn normalization ----------------
__global__ __launch_bounds__(256) void normalize_kernel(
    const int* __restrict__ dst,
    float* __restrict__ out_attn,
    int e)
{
    const int i = blockIdx.x * blockDim.x + threadIdx.x;
    if (i >= e) return;
    const int d = dst[i];
    const float4 i0 = *(const float4*)(g_inv + (size_t)d * HH);
    const float4 i1 = *(const float4*)(g_inv + (size_t)d * HH + 4);
    float4 a0 = __ldcs((const float4*)(out_attn + (size_t)i * HH));
    float4 a1 = __ldcs((const float4*)(out_attn + (size_t)i * HH + 4));
    a0.x *= i0.x; a0.y *= i0.y; a0.z *= i0.z; a0.w *= i0.w;
    a1.x *= i1.x; a1.y *= i1.y; a1.z *= i1.z; a1.w *= i1.w;
    __stcs((float4*)(out_attn + (size_t)i * HH),     a0);
    __stcs((float4*)(out_attn + (size_t)i * HH + 4), a1);
}

// ---------------- launch ----------------
extern "C" void kernel_launch(void* const* d_in, const int* in_sizes, int n_in,
                              void* d_out, int out_size)
{
    const float* x   = (const float*)d_in[0];
    const float* pi  = (const float*)d_in[1];
    const float* vw  = (const float*)d_in[2];
    const float* Wq  = (const float*)d_in[3];
    const float* bq  = (const float*)d_in[4];
    const float* Wk  = (const float*)d_in[5];
    const float* bk  = (const float*)d_in[6];
    const float* Wv  = (const float*)d_in[7];
    const float* bv  = (const float*)d_in[8];
    const int*   src = (const int*)d_in[9];
    const int*   dst = (const int*)d_in[10];

    const int n = in_sizes[0] / DM;    // nodes
    const int e = in_sizes[10];        // edges

    float* out  = (float*)d_out;
    float* attn = out + (size_t)n * DM;

    int gb = (e / 4 + 255) / 256;
    if (gb > 2048) gb = 2048;

    const int nb = (n + 1023) / 1024;  // scan blocks (<=128)

    cudaFuncSetAttribute(qkv_mma_kernel, cudaFuncAttributeMaxDynamicSharedMemorySize, QKV_SMEM_BYTES);

    // W prep + tensor-core QKV projection
    prep_w_kernel<<<(6 * 16384 + 255) / 256, 256>>>(Wq, Wk, Wv);
    qkv_mma_kernel<<<(n + 127) / 128, 256, QKV_SMEM_BYTES>>>(x, bq, bk, bv, n);

    // CSR by dst (parallel 3-phase scan)
    zero_count_kernel<<<(n + 255) / 256, 256>>>(n);
    hist_kernel<<<gb, 256>>>(dst, e);
    blockscan_kernel<<<nb, 1024>>>(n);
    bsumscan_kernel<<<1, 32>>>(nb, n);
    addoff_kernel<<<(n + 255) / 256, 256>>>(n);
    scatter_kernel<<<gb, 256>>>(src, dst, e);

    // single-pass fused scores + softmax + aggregation
    node_kernel<<<(n + 7) / 8, 256>>>(pi, vw, out, attn, n);

    // edge-parallel attn normalization
    normalize_kernel<<<(e + 255) / 256, 256>>>(dst, attn, e);
}

// round 11
// speedup vs baseline: 1.0264x; 1.0264x over previous
#include <cuda_runtime.h>
#include <cuda_fp16.h>
#include <cuda_bf16.h>
#include <cstdint>

// Problem constants (fixed instance)
#define DM   128      // model dim
#define HH   8        // heads
#define MV   3        // views
#define MAXN 100000
#define MAXE 1600000

typedef unsigned long long ull;

// ---------------- scratch (static __device__ — no allocations) ----------------
__device__ float  g_q[(size_t)MAXN * DM];
// interleaved K/V in fp16: per node, 32 slots of 16B: {k01,k23,v01,v23}
__device__ uint4  g_kv[(size_t)MAXN * 32];
__device__ float  g_inv[(size_t)MAXN * HH];  // per (node, head) 1/sum
__device__ int    g_count[MAXN];
__device__ int    g_rowptr[MAXN + 1];
__device__ int    g_rowfill[MAXN];
__device__ int    g_bsum[128];
__device__ int    g_boff[128];
__device__ int2   g_elist[MAXE];             // (edge_id, src)
// W^T tiles, bf16: [mat(3)][split(2)][n(128)][k(128)]
__device__ __nv_bfloat16 g_wt[6 * 16384];

__device__ __forceinline__ uint32_t packbf2(float a, float b) {
    __nv_bfloat162 t = __floats2bfloat162_rn(a, b);
    return *(uint32_t*)&t;
}

// ---------------- W prep: transpose + bf16 hi/lo split ----------------
__global__ void prep_w_kernel(const float* __restrict__ Wq, const float* __restrict__ Wk,
                              const float* __restrict__ Wv) {
    const int idx = blockIdx.x * blockDim.x + threadIdx.x;
    if (idx >= 6 * 16384) return;
    const int ms  = idx >> 14;         // mat*2 + split
    const int rem = idx & 16383;
    const int nrow = rem >> 7;         // output column (B row) 0..127
    const int kcol = rem & 127;        // K 0..127
    const int m = ms >> 1, s = ms & 1;
    const float* W = (m == 0) ? Wq : ((m == 1) ? Wk : Wv);
    const float val = W[kcol * DM + nrow];   // stored as WT[n][k]
    __nv_bfloat16 h = __float2bfloat16(val);
    if (s == 1) h = __float2bfloat16(val - __bfloat162float(h));
    g_wt[(size_t)ms * 16384 + nrow * 128 + kcol] = h;
}

// ---------------- tensor-core QKV via baseline mma.sync (bf16 split, f32 accum) ----------------
#define XPAD 136
#define QKV_SMEM_ELEMS (4 * 128 * XPAD)
#define QKV_SMEM_BYTES (QKV_SMEM_ELEMS * 2)

__device__ __forceinline__ void mma16816(float* c, const uint32_t* a, const uint32_t* b) {
    asm volatile(
        "mma.sync.aligned.m16n8k16.row.col.f32.bf16.bf16.f32 "
        "{%0,%1,%2,%3}, {%4,%5,%6,%7}, {%8,%9}, {%0,%1,%2,%3};"
        : "+f"(c[0]), "+f"(c[1]), "+f"(c[2]), "+f"(c[3])
        : "r"(a[0]), "r"(a[1]), "r"(a[2]), "r"(a[3]), "r"(b[0]), "r"(b[1]));
}

__global__ __launch_bounds__(256, 1) void qkv_mma_kernel(
    const float* __restrict__ x,
    const float* __restrict__ bq, const float* __restrict__ bk, const float* __restrict__ bv,
    int n)
{
    extern __shared__ __nv_bfloat16 sm[];
    __nv_bfloat16* sxh = sm;
    __nv_bfloat16* sxl = sm + 128 * XPAD;
    __nv_bfloat16* swh = sm + 2 * 128 * XPAD;
    __nv_bfloat16* swl = sm + 3 * 128 * XPAD;

    const int tid = threadIdx.x;
    const int wid = tid >> 5;
    const int lane = tid & 31;
    const int wm = wid & 1;
    const int wn = wid >> 1;
    const int g = lane >> 2;
    const int tig = lane & 3;
    const int row0 = blockIdx.x * 128;

    // phase 1: load X tile, bf16 hi/lo split into SMEM
    for (int t = tid; t < 128 * 32; t += 256) {
        const int r = t >> 5, c4 = (t & 31) * 4;
        const int row = row0 + r;
        float4 f = make_float4(0.f, 0.f, 0.f, 0.f);
        if (row < n) f = *(const float4*)(x + (size_t)row * DM + c4);
        const __nv_bfloat16 h0 = __float2bfloat16(f.x), h1 = __float2bfloat16(f.y);
        const __nv_bfloat16 h2 = __float2bfloat16(f.z), h3 = __float2bfloat16(f.w);
        const int base = r * XPAD + c4;
        *(uint32_t*)(sxh + base)     = packbf2(__bfloat162float(h0), __bfloat162float(h1));
        *(uint32_t*)(sxh + base + 2) = packbf2(__bfloat162float(h2), __bfloat162float(h3));
        *(uint32_t*)(sxl + base)     = packbf2(f.x - __bfloat162float(h0), f.y - __bfloat162float(h1));
        *(uint32_t*)(sxl + base + 2) = packbf2(f.z - __bfloat162float(h2), f.w - __bfloat162float(h3));
    }

    for (int m = 0; m < 3; m++) {
        __syncthreads();
        {
            const uint4* wh = (const uint4*)(g_wt + (size_t)(m * 2) * 16384);
            const uint4* wl = (const uint4*)(g_wt + (size_t)(m * 2 + 1) * 16384);
            for (int t = tid; t < 2048; t += 256) {
                const int r = t >> 4, seg = (t & 15) * 8;
                *(uint4*)(swh + r * XPAD + seg) = wh[t];
                *(uint4*)(swl + r * XPAD + seg) = wl[t];
            }
        }
        __syncthreads();

        float acc[4][4][4];
#pragma unroll
        for (int mf = 0; mf < 4; mf++)
#pragma unroll
            for (int nf = 0; nf < 4; nf++)
#pragma unroll
                for (int r = 0; r < 4; r++) acc[mf][nf][r] = 0.f;

#pragma unroll
        for (int s = 0; s < 3; s++) {  // (hi,hi), (hi,lo), (lo,hi)
            const __nv_bfloat16* A = (s == 2) ? sxl : sxh;
            const __nv_bfloat16* B = (s == 1) ? swl : swh;
#pragma unroll
            for (int ks = 0; ks < 8; ks++) {
                const int kb = ks * 16 + 2 * tig;
                uint32_t a[4][4], b[4][2];
#pragma unroll
                for (int mf = 0; mf < 4; mf++) {
                    const int ar = wm * 64 + mf * 16 + g;
                    a[mf][0] = *(const uint32_t*)(A + ar * XPAD + kb);
                    a[mf][1] = *(const uint32_t*)(A + (ar + 8) * XPAD + kb);
                    a[mf][2] = *(const uint32_t*)(A + ar * XPAD + kb + 8);
                    a[mf][3] = *(const uint32_t*)(A + (ar + 8) * XPAD + kb + 8);
                }
#pragma unroll
                for (int nf = 0; nf < 4; nf++) {
                    const int br = wn * 32 + nf * 8 + g;
                    b[nf][0] = *(const uint32_t*)(B + br * XPAD + kb);
                    b[nf][1] = *(const uint32_t*)(B + br * XPAD + kb + 8);
                }
#pragma unroll
                for (int mf = 0; mf < 4; mf++)
#pragma unroll
                    for (int nf = 0; nf < 4; nf++)
                        mma16816(acc[mf][nf], a[mf], b[nf]);
            }
        }

        const float* bias = (m == 0) ? bq : ((m == 1) ? bk : bv);
        const int hoff = (m == 1) ? 0 : 2;
#pragma unroll
        for (int mf = 0; mf < 4; mf++) {
            const int row = row0 + wm * 64 + mf * 16 + g;
#pragma unroll
            for (int nf = 0; nf < 4; nf++) {
                const int col = wn * 32 + nf * 8 + 2 * tig;
                const float bz0 = bias[col], bz1 = bias[col + 1];
                const float f0 = acc[mf][nf][0] + bz0, f1 = acc[mf][nf][1] + bz1;
                const float f2 = acc[mf][nf][2] + bz0, f3 = acc[mf][nf][3] + bz1;
                if (m == 0) {
                    if (row < n)     *(float2*)(g_q + (size_t)row * DM + col)       = make_float2(f0, f1);
                    if (row + 8 < n) *(float2*)(g_q + (size_t)(row + 8) * DM + col) = make_float2(f2, f3);
                } else {
                    const int word = hoff + ((col >> 1) & 1);
                    if (row < n)
                        ((__half2*)&g_kv[(size_t)row * 32 + (col >> 2)])[word] = __floats2half2_rn(f0, f1);
                    if (row + 8 < n)
                        ((__half2*)&g_kv[(size_t)(row + 8) * 32 + (col >> 2)])[word] = __floats2half2_rn(f2, f3);
                }
            }
        }
    }
}

// ---------------- CSR build ----------------
__global__ void zero_count_kernel(int n) {
    int i = blockIdx.x * blockDim.x + threadIdx.x;
    if (i < n) g_count[i] = 0;
}

// int4 loads: 4 destinations per thread
__global__ void hist_kernel(const int* __restrict__ dst, int e) {
    const int e4 = e >> 2;
    for (int i = blockIdx.x * blockDim.x + threadIdx.x; i < e4; i += gridDim.x * blockDim.x) {
        const int4 d = ((const int4*)dst)[i];
        atomicAdd(&g_count[d.x], 1);
        atomicAdd(&g_count[d.y], 1);
        atomicAdd(&g_count[d.z], 1);
        atomicAdd(&g_count[d.w], 1);
    }
    // tail
    const int base = e4 << 2;
    const int t = blockIdx.x * blockDim.x + threadIdx.x;
    if (t < e - base) atomicAdd(&g_count[dst[base + t]], 1);
}

__global__ __launch_bounds__(1024) void blockscan_kernel(int n) {
    __shared__ int s_wsum[32];
    const int tid = threadIdx.x;
    const int lane = tid & 31, wid = tid >> 5;
    const int i = blockIdx.x * 1024 + tid;
    int v = (i < n) ? g_count[i] : 0;
    int x = v;
#pragma unroll
    for (int o = 1; o < 32; o <<= 1) {
        int t = __shfl_up_sync(0xffffffffu, x, o);
        if (lane >= o) x += t;
    }
    if (lane == 31) s_wsum[wid] = x;
    __syncthreads();
    if (wid == 0) {
        int ws = s_wsum[lane];
#pragma unroll
        for (int o = 1; o < 32; o <<= 1) {
            int t = __shfl_up_sync(0xffffffffu, ws, o);
            if (lane >= o) ws += t;
        }
        s_wsum[lane] = ws;
    }
    __syncthreads();
    int excl = (wid ? s_wsum[wid - 1] : 0) + (x - v);
    if (i < n) g_rowptr[i] = excl;
    if (tid == 0) g_bsum[blockIdx.x] = s_wsum[31];
}

__global__ void bsumscan_kernel(int nb, int n) {
    const int lane = threadIdx.x;
    int carry = 0;
    for (int base = 0; base < nb; base += 32) {
        int idx = base + lane;
        int v = (idx < nb) ? g_bsum[idx] : 0;
        int x = v;
#pragma unroll
        for (int o = 1; o < 32; o <<= 1) {
            int t = __shfl_up_sync(0xffffffffu, x, o);
            if (lane >= o) x += t;
        }
        if (idx < nb) g_boff[idx] = carry + (x - v);
        carry += __shfl_sync(0xffffffffu, x, 31);
    }
    if (lane == 0) g_rowptr[n] = carry;
}

__global__ void addoff_kernel(int n) {
    int i = blockIdx.x * blockDim.x + threadIdx.x;
    if (i < n) {
        int r = g_rowptr[i] + g_boff[i >> 10];
        g_rowptr[i] = r;
        g_rowfill[i] = r;
    }
}

// int4 loads: 4 edges per thread
__global__ void scatter_kernel(const int* __restrict__ src, const int* __restrict__ dst, int e) {
    const int e4 = e >> 2;
    for (int i = blockIdx.x * blockDim.x + threadIdx.x; i < e4; i += gridDim.x * blockDim.x) {
        const int4 d = ((const int4*)dst)[i];
        const int4 s = ((const int4*)src)[i];
        const int eb = i << 2;
        g_elist[atomicAdd(&g_rowfill[d.x], 1)] = make_int2(eb,     s.x);
        g_elist[atomicAdd(&g_rowfill[d.y], 1)] = make_int2(eb + 1, s.y);
        g_elist[atomicAdd(&g_rowfill[d.z], 1)] = make_int2(eb + 2, s.z);
        g_elist[atomicAdd(&g_rowfill[d.w], 1)] = make_int2(eb + 3, s.w);
    }
    const int base = e4 << 2;
    const int t = blockIdx.x * blockDim.x + threadIdx.x;
    if (t < e - base) {
        const int i = base + t;
        g_elist[atomicAdd(&g_rowfill[dst[i]], 1)] = make_int2(i, src[i]);
    }
}

// ---------------- single-pass node kernel: 4-edge unroll, cached loads ----------------
// One warp per node. Lane l owns features [4l,4l+4), head h = l>>2.
// Loads (elist, q, view_w, kv) use default .ca; only stores use .cs.
__global__ __launch_bounds__(256) void node_kernel(
    const float* __restrict__ pi,
    const float* __restrict__ view_w,
    float* __restrict__ out_states,   // [N, 128]
    float* __restrict__ out_attn,     // [E, 8] (unnormalized here)
    int n)
{
    const int nd = blockIdx.x * (blockDim.x >> 5) + (threadIdx.x >> 5);
    if (nd >= n) return;
    const int lane = threadIdx.x & 31;
    const unsigned FULL = 0xffffffffu;

    const int beg = g_rowptr[nd];
    const int end = g_rowptr[nd + 1];

    const float4 qv = *(const float4*)(g_q + (size_t)nd * DM + lane * 4);
    const int h = lane >> 2;
    const float* pip = pi + (size_t)nd * (HH * MV) + h * MV;
    const float pi0 = pip[0], pi1 = pip[1], pi2 = pip[2];

    float ssum = 0.f;
    float4 acc = make_float4(0.f, 0.f, 0.f, 0.f);
    const int wsrc = (lane & 7) * 4;   // shuffle source for per-head w

    int i = beg;
    const int end4 = beg + ((end - beg) & ~3);
    for (; i < end4; i += 4) {
        // front-batched loads: 4 elist + 4 kv gathers in flight
        const int2 e0 = g_elist[i];
        const int2 e1 = g_elist[i + 1];
        const int2 e2 = g_elist[i + 2];
        const int2 e3 = g_elist[i + 3];
        const uint4 kv0 = g_kv[(size_t)e0.y * 32 + lane];
        const uint4 kv1 = g_kv[(size_t)e1.y * 32 + lane];
        const uint4 kv2 = g_kv[(size_t)e2.y * 32 + lane];
        const uint4 kv3 = g_kv[(size_t)e3.y * 32 + lane];
        const float* vw0 = view_w + (size_t)e0.x * MV;
        const float* vw1 = view_w + (size_t)e1.x * MV;
        const float* vw2 = view_w + (size_t)e2.x * MV;
        const float* vw3 = view_w + (size_t)e3.x * MV;
        const float mix0 = pi0 * vw0[0] + pi1 * vw0[1] + pi2 * vw0[2];
        const float mix1 = pi0 * vw1[0] + pi1 * vw1[1] + pi2 * vw1[2];
        const float mix2 = pi0 * vw2[0] + pi1 * vw2[1] + pi2 * vw2[2];
        const float mix3 = pi0 * vw3[0] + pi1 * vw3[1] + pi2 * vw3[2];

        float2 ka, kb;
        ka = __half22float2(*(const __half2*)&kv0.x); kb = __half22float2(*(const __half2*)&kv0.y);
        float p0 = qv.x * ka.x + qv.y * ka.y + qv.z * kb.x + qv.w * kb.y;
        ka = __half22float2(*(const __half2*)&kv1.x); kb = __half22float2(*(const __half2*)&kv1.y);
        float p1 = qv.x * ka.x + qv.y * ka.y + qv.z * kb.x + qv.w * kb.y;
        ka = __half22float2(*(const __half2*)&kv2.x); kb = __half22float2(*(const __half2*)&kv2.y);
        float p2 = qv.x * ka.x + qv.y * ka.y + qv.z * kb.x + qv.w * kb.y;
        ka = __half22float2(*(const __half2*)&kv3.x); kb = __half22float2(*(const __half2*)&kv3.y);
        float p3 = qv.x * ka.x + qv.y * ka.y + qv.z * kb.x + qv.w * kb.y;

        p0 += __shfl_xor_sync(FULL, p0, 1);
        p1 += __shfl_xor_sync(FULL, p1, 1);
        p2 += __shfl_xor_sync(FULL, p2, 1);
        p3 += __shfl_xor_sync(FULL, p3, 1);
        p0 += __shfl_xor_sync(FULL, p0, 2);
        p1 += __shfl_xor_sync(FULL, p1, 2);
        p2 += __shfl_xor_sync(FULL, p2, 2);
        p3 += __shfl_xor_sync(FULL, p3, 2);

        const float w0 = (mix0 > 0.f) ? __expf(p0 * 0.25f) * fmaxf(mix0, 1e-8f) : 0.f;
        const float w1 = (mix1 > 0.f) ? __expf(p1 * 0.25f) * fmaxf(mix1, 1e-8f) : 0.f;
        const float w2 = (mix2 > 0.f) ? __expf(p2 * 0.25f) * fmaxf(mix2, 1e-8f) : 0.f;
        const float w3 = (mix3 > 0.f) ? __expf(p3 * 0.25f) * fmaxf(mix3, 1e-8f) : 0.f;
        ssum += (w0 + w1) + (w2 + w3);

        const float wl0 = __shfl_sync(FULL, w0, wsrc);
        const float wl1 = __shfl_sync(FULL, w1, wsrc);
        const float wl2 = __shfl_sync(FULL, w2, wsrc);
        const float wl3 = __shfl_sync(FULL, w3, wsrc);
        if (lane < 8) {
            __stcs(&out_attn[(size_t)e0.x * HH + lane], wl0);
            __stcs(&out_attn[(size_t)e1.x * HH + lane], wl1);
            __stcs(&out_attn[(size_t)e2.x * HH + lane], wl2);
            __stcs(&out_attn[(size_t)e3.x * HH + lane], wl3);
        }

        float2 va, vb;
        va = __half22float2(*(const __half2*)&kv0.z); vb = __half22float2(*(const __half2*)&kv0.w);
        acc.x += va.x * w0; acc.y += va.y * w0; acc.z += vb.x * w0; acc.w += vb.y * w0;
        va = __half22float2(*(const __half2*)&kv1.z); vb = __half22float2(*(const __half2*)&kv1.w);
        acc.x += va.x * w1; acc.y += va.y * w1; acc.z += vb.x * w1; acc.w += vb.y * w1;
        va = __half22float2(*(const __half2*)&kv2.z); vb = __half22float2(*(const __half2*)&kv2.w);
        acc.x += va.x * w2; acc.y += va.y * w2; acc.z += vb.x * w2; acc.w += vb.y * w2;
        va = __half22float2(*(const __half2*)&kv3.z); vb = __half22float2(*(const __half2*)&kv3.w);
        acc.x += va.x * w3; acc.y += va.y * w3; acc.z += vb.x * w3; acc.w += vb.y * w3;
    }
    for (; i < end; i++) {
        const int2 e0 = g_elist[i];
        const uint4 kv0 = g_kv[(size_t)e0.y * 32 + lane];
        const float* vw0 = view_w + (size_t)e0.x * MV;
        const float mix0 = pi0 * vw0[0] + pi1 * vw0[1] + pi2 * vw0[2];
        const float2 ka = __half22float2(*(const __half2*)&kv0.x);
        const float2 kb = __half22float2(*(const __half2*)&kv0.y);
        float p0 = qv.x * ka.x + qv.y * ka.y + qv.z * kb.x + qv.w * kb.y;
        p0 += __shfl_xor_sync(FULL, p0, 1);
        p0 += __shfl_xor_sync(FULL, p0, 2);
        const float w0 = (mix0 > 0.f) ? __expf(p0 * 0.25f) * fmaxf(mix0, 1e-8f) : 0.f;
        ssum += w0;
        const float wl0 = __shfl_sync(FULL, w0, wsrc);
        if (lane < 8) __stcs(&out_attn[(size_t)e0.x * HH + lane], wl0);
        const float2 va = __half22float2(*(const __half2*)&kv0.z);
        const float2 vb = __half22float2(*(const __half2*)&kv0.w);
        acc.x += va.x * w0; acc.y += va.y * w0; acc.z += vb.x * w0; acc.w += vb.y * w0;
    }

    const float inv = 1.f / fmaxf(ssum, 1e-8f);
    acc.x *= inv; acc.y *= inv; acc.z *= inv; acc.w *= inv;
    __stcs((float4*)(out_states + (size_t)nd * DM + lane * 4), acc);

    const float inv_h = __shfl_sync(FULL, inv, lane * 4);  // valid for lane<8
    if (lane < 8) g_inv[(size_t)nd * HH + lane] = inv_h;
}

// ---------------- edge-parallel attn normalization ----------------
__global__ __launch_bounds__(256) void normalize_kernel(
    const int* __restrict__ dst,
    float* __restrict__ out_attn,
    int e)
{
    const int i = blockIdx.x * blockDim.x + threadIdx.x;
    if (i >= e) return;
    const int d = dst[i];
    const float4 i0 = *(const float4*)(g_inv + (size_t)d * HH);
    const float4 i1 = *(const float4*)(g_inv + (size_t)d * HH + 4);
    float4 a0 = *(const float4*)(out_attn + (size_t)i * HH);
    float4 a1 = *(const float4*)(out_attn + (size_t)i * HH + 4);
    a0.x *= i0.x; a0.y *= i0.y; a0.z *= i0.z; a0.w *= i0.w;
    a1.x *= i1.x; a1.y *= i1.y; a1.z *= i1.z; a1.w *= i1.w;
    __stcs((float4*)(out_attn + (size_t)i * HH),     a0);
    __stcs((float4*)(out_attn + (size_t)i * HH + 4), a1);
}

// ---------------- launch ----------------
extern "C" void kernel_launch(void* const* d_in, const int* in_sizes, int n_in,
                              void* d_out, int out_size)
{
    const float* x   = (const float*)d_in[0];
    const float* pi  = (const float*)d_in[1];
    const float* vw  = (const float*)d_in[2];
    const float* Wq  = (const float*)d_in[3];
    const float* bq  = (const float*)d_in[4];
    const float* Wk  = (const float*)d_in[5];
    const float* bk  = (const float*)d_in[6];
    const float* Wv  = (const float*)d_in[7];
    const float* bv  = (const float*)d_in[8];
    const int*   src = (const int*)d_in[9];
    const int*   dst = (const int*)d_in[10];

    const int n = in_sizes[0] / DM;    // nodes
    const int e = in_sizes[10];        // edges

    float* out  = (float*)d_out;
    float* attn = out + (size_t)n * DM;

    int gb = (e / 4 + 255) / 256;
    if (gb > 2048) gb = 2048;

    const int nb = (n + 1023) / 1024;  // scan blocks (<=128)

    cudaFuncSetAttribute(qkv_mma_kernel, cudaFuncAttributeMaxDynamicSharedMemorySize, QKV_SMEM_BYTES);

    // W prep + tensor-core QKV projection
    prep_w_kernel<<<(6 * 16384 + 255) / 256, 256>>>(Wq, Wk, Wv);
    qkv_mma_kernel<<<(n + 127) / 128, 256, QKV_SMEM_BYTES>>>(x, bq, bk, bv, n);

    // CSR by dst (parallel 3-phase scan)
    zero_count_kernel<<<(n + 255) / 256, 256>>>(n);
    hist_kernel<<<gb, 256>>>(dst, e);
    blockscan_kernel<<<nb, 1024>>>(n);
    bsumscan_kernel<<<1, 32>>>(nb, n);
    addoff_kernel<<<(n + 255) / 256, 256>>>(n);
    scatter_kernel<<<gb, 256>>>(src, dst, e);

    // single-pass fused scores + softmax + aggregation
    node_kernel<<<(n + 7) / 8, 256>>>(pi, vw, out, attn, n);

    // edge-parallel attn normalization
    normalize_kernel<<<(e + 255) / 256, 256>>>(dst, attn, e);
}